// round 14
// baseline (speedup 1.0000x reference)
#include <cuda_runtime.h>
#include <cuda_bf16.h>
#include <cuda_fp16.h>
#include <math.h>

#define ME   128
#define MN   128
#define NDET 32
#define NO   (NDET*ME)
#define LOG2E 1.4426950408889634f
#define NBLK 296          // 2 blocks/SM * 148 SMs -> exactly one wave
#define BPS  148

#define ROWP 132          // padded row: stride = 4 banks -> conflict-free LDS.128
#define OFF_SZL (ME*ROWP)
#define OFF_SPI (OFF_SZL + 16*ROWP)
#define OFF_SFE (OFF_SPI + 16*ROWP)
#define OFF_SNC (OFF_SFE + 128*4)
#define OFF_SEC (OFF_SNC + 128*4)
#define SMEM_FLOATS (OFF_SEC + 128*4)   // 90624 B -> 2 blocks/SM

// Two exp2 per MUFU slot: pack f32 pair -> f16x2, ex2.approx.f16x2, unpack.
__device__ __forceinline__ float2 ex2_pair(float x0, float x1) {
    __half2 h = __floats2half2_rn(x0, x1);
    h = h2exp2(h);
    return __half22float2(h);
}

// All-FMA/ALU sqrt: Quake rsqrt seed + 2 Newton iters (rel err ~3e-9).
__device__ __forceinline__ float sqrt_fma(float x) {
    x = fmaxf(x, 1e-20f);
    float y = __int_as_float(0x5f3759df - (__float_as_int(x) >> 1));
    float nh = -0.5f * x;
    y = y * fmaf(nh, y * y, 1.5f);
    y = y * fmaf(nh, y * y, 1.5f);
    return x * y;
}

__device__ __forceinline__ unsigned char mask_val(const unsigned char* p, int i, int mode) {
    if (mode == 2) return (((const float*)p)[i] != 0.0f);
    if (mode == 1) return (((const int*)p)[i] != 0);
    if (mode == 3) return 0;
    return (p[i] != 0);
}

// 4-lane hybrid accumulate: 2 MUFU f16x2 ops cover 4 exps.
__device__ __forceinline__ void acc4h(float4 d, float4 z, float4 p, float& a) {
    float2 e01 = ex2_pair(d.x * z.x, d.y * z.y);
    float2 e23 = ex2_pair(d.z * z.z, d.w * z.w);
    a = fmaf(p.x, e01.x, a);
    a = fmaf(p.y, e01.y, a);
    a = fmaf(p.z, e23.x, a);
    a = fmaf(p.w, e23.y, a);
}

__global__ void __launch_bounds__(256, 2) k_fused(
        const float* __restrict__ up, const float* __restrict__ dn,
        const float* __restrict__ nc, const float* __restrict__ q,
        const float* __restrict__ Wpu, const float* __restrict__ Wzu,
        const float* __restrict__ Wpd, const float* __restrict__ Wzd,
        const unsigned char* __restrict__ um, const unsigned char* __restrict__ dm,
        const unsigned char* __restrict__ nm, float* __restrict__ out) {
    extern __shared__ float smem[];
    float* sd  = smem;
    float* szl = smem + OFF_SZL;
    float* spi = smem + OFF_SPI;
    float* sfe = smem + OFF_SFE;
    float* snc = smem + OFF_SNC;
    float* sec = smem + OFF_SEC;
    __shared__ int   smode[2];
    __shared__ float spart[4][4];
    __shared__ unsigned char sem[128];
    __shared__ unsigned char snm[128];
    __shared__ float smean[3];

    int bx  = blockIdx.x;
    int s   = (bx >= BPS) ? 1 : 0;
    int bl  = bx - s * BPS;
    int tid = threadIdx.x;
    int lane = tid & 31;

    int o_start = (bl * NO) / BPS;       // ragged 27/28-orbital range
    int o_end   = ((bl + 1) * NO) / BPS;

    const float* ec = s ? dn : up;
    const float* Wp = s ? Wpd : Wpu;     // zeta from W_pi
    const float* Wz = s ? Wzd : Wzu;     // pi from W_zeta
    const unsigned char* emp = s ? dm : um;

    // --- mask-mode detection: ballot-based, warps 0 and 4 ---
    if (tid < 32 || (tid >= 128 && tid < 160)) {
        const unsigned char* p = (tid < 32) ? emp : nm;
        unsigned int w = ((const unsigned int*)p)[lane];
        unsigned int ex = w & 0x7F800000u;
        bool isf = (w == 0x3F800000u) || (ex >= 0x38000000u && ex <= 0x47000000u);
        unsigned anyF  = __ballot_sync(0xFFFFFFFFu, isf);
        unsigned anyNZ = __ballot_sync(0xFFFFFFFFu, w != 0u);
        unsigned small = __ballot_sync(0xFFFFFFFFu, w <= 1u);
        if (lane == 0) {
            int mode;
            if (!anyNZ)                     mode = 3;
            else if (anyF)                  mode = 2;
            else if (small == 0xFFFFFFFFu)  mode = 1;
            else                            mode = 0;
            smode[tid < 32 ? 0 : 1] = mode;
        }
    }
    __syncthreads();
    if (tid < 128)       sem[tid]       = mask_val(emp, tid, smode[0]);
    else                 snm[tid - 128] = mask_val(nm, tid - 128, smode[1]);
    __syncthreads();

    // --- stage coords; masked mean via warp shuffles ---
    if (tid < 128) {
        float m = snm[tid] ? 1.0f : 0.0f;
        float x = nc[3*tid+0], y = nc[3*tid+1], z = nc[3*tid+2];
        snc[4*tid+0] = x; snc[4*tid+1] = y; snc[4*tid+2] = z; snc[4*tid+3] = m;
        sec[4*tid+0] = ec[3*tid+0]; sec[4*tid+1] = ec[3*tid+1]; sec[4*tid+2] = ec[3*tid+2];
        float xm = x * m, ym = y * m, zm = z * m, cm = m;
        #pragma unroll
        for (int off = 16; off > 0; off >>= 1) {
            xm += __shfl_down_sync(0xFFFFFFFFu, xm, off);
            ym += __shfl_down_sync(0xFFFFFFFFu, ym, off);
            zm += __shfl_down_sync(0xFFFFFFFFu, zm, off);
            cm += __shfl_down_sync(0xFFFFFFFFu, cm, off);
        }
        if (lane == 0) {
            int w = tid >> 5;
            spart[w][0] = xm; spart[w][1] = ym; spart[w][2] = zm; spart[w][3] = cm;
        }
    }
    __syncthreads();
    if (tid == 0) {
        float x = spart[0][0] + spart[1][0] + spart[2][0] + spart[3][0];
        float y = spart[0][1] + spart[1][1] + spart[2][1] + spart[3][1];
        float z = spart[0][2] + spart[1][2] + spart[2][2] + spart[3][2];
        float c = fmaxf(spart[0][3] + spart[1][3] + spart[2][3] + spart[3][3], 1.0f);
        smean[0] = x / c; smean[1] = y / c; smean[2] = z / c;
    }
    __syncthreads();
    if (tid < 128) {
        float m = snc[4*tid+3];
        sfe[4*tid+0] = q[tid] * m;
        sfe[4*tid+1] = (snc[4*tid+0] - smean[0]) * m;
        sfe[4*tid+2] = (snc[4*tid+1] - smean[1]) * m;
        sfe[4*tid+3] = (snc[4*tid+2] - smean[2]) * m;
    }

    // --- dist tile [128 e][128 n] (sqrt on FMA/ALU pipes) ---
    #pragma unroll
    for (int i = tid; i < ME * MN; i += 256) {
        int e = i >> 7, n = i & 127;
        float dx = sec[4*e+0] - snc[4*n+0];
        float dy = sec[4*e+1] - snc[4*n+1];
        float dz = sec[4*e+2] - snc[4*n+2];
        sd[e * ROWP + n] = sqrt_fma(fmaf(dx, dx, fmaf(dy, dy, dz*dz)));
    }
    __syncthreads();

    // ========== chunk 0: 16 orbitals at o_start ==========
    #pragma unroll
    for (int j = tid; j < 16 * MN; j += 256) {
        int ol = j >> 7, n = j & 127;
        int o  = o_start + ol;
        float f0 = sfe[4*n+0], f1 = sfe[4*n+1], f2 = sfe[4*n+2], f3 = sfe[4*n+3];
        float zeta = fmaf(f0, Wp[o], fmaf(f1, Wp[NO+o], fmaf(f2, Wp[2*NO+o], f3 * Wp[3*NO+o])));
        float pi   = fmaf(f0, Wz[o], fmaf(f1, Wz[NO+o], fmaf(f2, Wz[2*NO+o], f3 * Wz[3*NO+o])));
        szl[ol * ROWP + n] = -fabsf(zeta) * LOG2E;
        spi[ol * ROWP + n] = pi;
    }
    __syncthreads();

    {   // map A: 4e x 2o per thread, f16x2 exp (2 elems per MUFU slot)
        int eg = tid >> 3, og = tid & 7;
        float acc[4][2];
        #pragma unroll
        for (int ei = 0; ei < 4; ei++)
            #pragma unroll
            for (int oj = 0; oj < 2; oj++) acc[ei][oj] = 0.0f;
        const float* sd0 = sd  + eg * ROWP;
        const float* z0  = szl + og * ROWP;
        const float* p0  = spi + og * ROWP;
        #pragma unroll 4
        for (int c = 0; c < 32; c++) {
            float4 d0 = *(const float4*)(sd0 +  0 * ROWP + c * 4);
            float4 d1 = *(const float4*)(sd0 + 32 * ROWP + c * 4);
            float4 d2 = *(const float4*)(sd0 + 64 * ROWP + c * 4);
            float4 d3 = *(const float4*)(sd0 + 96 * ROWP + c * 4);
            #pragma unroll
            for (int oj = 0; oj < 2; oj++) {
                float4 z = *(const float4*)(z0 + oj * 8 * ROWP + c * 4);
                float4 p = *(const float4*)(p0 + oj * 8 * ROWP + c * 4);
                acc4h(d0, z, p, acc[0][oj]);
                acc4h(d1, z, p, acc[1][oj]);
                acc4h(d2, z, p, acc[2][oj]);
                acc4h(d3, z, p, acc[3][oj]);
            }
        }
        #pragma unroll
        for (int ei = 0; ei < 4; ei++) {
            int e = eg + 32 * ei;
            bool eok = (sem[e] != 0);
            #pragma unroll
            for (int oj = 0; oj < 2; oj++) {
                int o = o_start + og + 8 * oj;
                int d = o >> 7, m = o & 127;
                float v = (eok && (sem[m] != 0)) ? acc[ei][oj]
                                                 : (e == m ? 1.0f : 0.0f);
                out[(((s << 5) + d) << 14) + (e << 7) + m] = v;
            }
        }
    }
    __syncthreads();

    // ========== chunk 1: up to 12 orbitals at o_start+16 ==========
    int cw = o_end - (o_start + 16);
    #pragma unroll
    for (int j = tid; j < 12 * MN; j += 256) {
        int ol = j >> 7, n = j & 127;
        int o  = o_start + 16 + ol;
        float zl = 0.0f, pi = 0.0f;
        if (ol < cw) {
            float f0 = sfe[4*n+0], f1 = sfe[4*n+1], f2 = sfe[4*n+2], f3 = sfe[4*n+3];
            float zeta = fmaf(f0, Wp[o], fmaf(f1, Wp[NO+o], fmaf(f2, Wp[2*NO+o], f3 * Wp[3*NO+o])));
            pi   = fmaf(f0, Wz[o], fmaf(f1, Wz[NO+o], fmaf(f2, Wz[2*NO+o], f3 * Wz[3*NO+o])));
            zl   = -fabsf(zeta) * LOG2E;
        }
        szl[ol * ROWP + n] = zl;
        spi[ol * ROWP + n] = pi;
    }
    __syncthreads();

    {   // map B: 2e x 3o per thread, f16x2 exp
        int eg2 = tid >> 2, og2 = tid & 3;
        float acc[2][3];
        #pragma unroll
        for (int ei = 0; ei < 2; ei++)
            #pragma unroll
            for (int oj = 0; oj < 3; oj++) acc[ei][oj] = 0.0f;
        const float* sd0 = sd  + eg2 * ROWP;
        const float* z0  = szl + og2 * ROWP;
        const float* p0  = spi + og2 * ROWP;
        #pragma unroll 4
        for (int c = 0; c < 32; c++) {
            float4 d0 = *(const float4*)(sd0 +  0 * ROWP + c * 4);
            float4 d1 = *(const float4*)(sd0 + 64 * ROWP + c * 4);
            #pragma unroll
            for (int oj = 0; oj < 3; oj++) {
                float4 z = *(const float4*)(z0 + oj * 4 * ROWP + c * 4);
                float4 p = *(const float4*)(p0 + oj * 4 * ROWP + c * 4);
                acc4h(d0, z, p, acc[0][oj]);
                acc4h(d1, z, p, acc[1][oj]);
            }
        }
        #pragma unroll
        for (int ei = 0; ei < 2; ei++) {
            int e = eg2 + 64 * ei;
            bool eok = (sem[e] != 0);
            #pragma unroll
            for (int oj = 0; oj < 3; oj++) {
                int ol = og2 + 4 * oj;
                if (ol < cw) {
                    int o = o_start + 16 + ol;
                    int d = o >> 7, m = o & 127;
                    float v = (eok && (sem[m] != 0)) ? acc[ei][oj]
                                                     : (e == m ? 1.0f : 0.0f);
                    out[(((s << 5) + d) << 14) + (e << 7) + m] = v;
                }
            }
        }
    }
}

// ---------------------------------------------------------------------------
extern "C" void kernel_launch(void* const* d_in, const int* in_sizes, int n_in,
                              void* d_out, int out_size) {
    const float* up  = (const float*)d_in[0];
    const float* dn  = (const float*)d_in[1];
    const float* nc  = (const float*)d_in[2];
    const float* q   = (const float*)d_in[3];
    const float* Wpu = (const float*)d_in[4];
    const float* Wzu = (const float*)d_in[5];
    const float* Wpd = (const float*)d_in[6];
    const float* Wzd = (const float*)d_in[7];
    const unsigned char* um = (const unsigned char*)d_in[8];
    const unsigned char* dm = (const unsigned char*)d_in[9];
    const unsigned char* nm = (const unsigned char*)d_in[10];
    float* out = (float*)d_out;

    cudaFuncSetAttribute(k_fused, cudaFuncAttributeMaxDynamicSharedMemorySize,
                         SMEM_FLOATS * sizeof(float));
    k_fused<<<NBLK, 256, SMEM_FLOATS * sizeof(float)>>>(
        up, dn, nc, q, Wpu, Wzu, Wpd, Wzd, um, dm, nm, out);
}

// round 15
// speedup vs baseline: 1.1838x; 1.1838x over previous
#include <cuda_runtime.h>
#include <cuda_bf16.h>
#include <cuda_fp16.h>
#include <math.h>

#define ME   128
#define MN   128
#define NDET 32
#define NO   (NDET*ME)
#define LOG2E 1.4426950408889634f
#define NBLK 296          // 2 blocks/SM * 148 SMs -> exactly one wave
#define BPS  148

#define ROWH 68           // half2 per row (272 B): bank stride 4 -> conflict-free
// 4-byte-unit offsets (half2 and float are both 4 B)
#define H_SD  0
#define H_SZL (128*ROWH)            // 8704
#define H_SPI (H_SZL + 28*ROWH)     // 10608
#define H_END (H_SPI + 28*ROWH)     // 12512
#define SMEM_FLOATS (H_END + 3*512) // 14048 floats = 56192 B -> 2 blocks/SM easily

// All-FMA/ALU sqrt: Quake rsqrt seed + 2 Newton iters (rel err ~3e-9).
__device__ __forceinline__ float sqrt_fma(float x) {
    x = fmaxf(x, 1e-20f);
    float y = __int_as_float(0x5f3759df - (__float_as_int(x) >> 1));
    float nh = -0.5f * x;
    y = y * fmaf(nh, y * y, 1.5f);
    y = y * fmaf(nh, y * y, 1.5f);
    return x * y;
}

__device__ __forceinline__ unsigned char mask_val(const unsigned char* p, int i, int mode) {
    if (mode == 2) return (((const float*)p)[i] != 0.0f);
    if (mode == 1) return (((const int*)p)[i] != 0);
    if (mode == 3) return 0;
    return (p[i] != 0);
}

// 8-element cell step: 4x (HMUL2 -> MUFU.EX2.f16x2 -> HFMA2), flush to f32.
// All operands already fp16 in smem -> ZERO per-element conversions.
__device__ __forceinline__ float cell8(float4 dv, float4 zv, float4 pv) {
    const __half2* dh = (const __half2*)&dv;
    const __half2* zh = (const __half2*)&zv;
    const __half2* ph = (const __half2*)&pv;
    __half2 a = __floats2half2_rn(0.0f, 0.0f);
    #pragma unroll
    for (int k = 0; k < 4; k++)
        a = __hfma2(ph[k], h2exp2(__hmul2(dh[k], zh[k])), a);
    float2 f = __half22float2(a);
    return f.x + f.y;
}

__global__ void __launch_bounds__(256, 2) k_fused(
        const float* __restrict__ up, const float* __restrict__ dn,
        const float* __restrict__ nc, const float* __restrict__ q,
        const float* __restrict__ Wpu, const float* __restrict__ Wzu,
        const float* __restrict__ Wpd, const float* __restrict__ Wzd,
        const unsigned char* __restrict__ um, const unsigned char* __restrict__ dm,
        const unsigned char* __restrict__ nm, float* __restrict__ out) {
    extern __shared__ float smem[];
    __half2* sdh  = (__half2*)smem + H_SD;    // [128][68] dist pairs
    __half2* szlh = (__half2*)smem + H_SZL;   // [28][68]
    __half2* spih = (__half2*)smem + H_SPI;   // [28][68]
    float* sfe = smem + H_END;                // [128][4]
    float* snc = sfe + 512;
    float* sec = snc + 512;
    __shared__ int   smode[2];
    __shared__ float spart[4][4];
    __shared__ unsigned char sem[128];
    __shared__ unsigned char snm[128];
    __shared__ float smean[3];

    int bx  = blockIdx.x;
    int s   = (bx >= BPS) ? 1 : 0;
    int bl  = bx - s * BPS;
    int tid = threadIdx.x;
    int lane = tid & 31;

    int o_start = (bl * NO) / BPS;       // ragged 27/28-orbital range
    int ow      = ((bl + 1) * NO) / BPS - o_start;

    const float* ec = s ? dn : up;
    const float* Wp = s ? Wpd : Wpu;     // zeta from W_pi
    const float* Wz = s ? Wzd : Wzu;     // pi from W_zeta
    const unsigned char* emp = s ? dm : um;

    // --- mask-mode detection: ballot-based, warps 0 and 4 ---
    if (tid < 32 || (tid >= 128 && tid < 160)) {
        const unsigned char* p = (tid < 32) ? emp : nm;
        unsigned int w = ((const unsigned int*)p)[lane];
        unsigned int ex = w & 0x7F800000u;
        bool isf = (w == 0x3F800000u) || (ex >= 0x38000000u && ex <= 0x47000000u);
        unsigned anyF  = __ballot_sync(0xFFFFFFFFu, isf);
        unsigned anyNZ = __ballot_sync(0xFFFFFFFFu, w != 0u);
        unsigned small = __ballot_sync(0xFFFFFFFFu, w <= 1u);
        if (lane == 0) {
            int mode;
            if (!anyNZ)                     mode = 3;
            else if (anyF)                  mode = 2;
            else if (small == 0xFFFFFFFFu)  mode = 1;
            else                            mode = 0;
            smode[tid < 32 ? 0 : 1] = mode;
        }
    }
    __syncthreads();
    if (tid < 128)       sem[tid]       = mask_val(emp, tid, smode[0]);
    else                 snm[tid - 128] = mask_val(nm, tid - 128, smode[1]);
    __syncthreads();

    // --- stage coords; masked mean via warp shuffles (scratch in sdh area) ---
    float* rx = smem; float* ry = smem + 128; float* rz = smem + 256; float* rc = smem + 384;
    (void)rx; (void)ry; (void)rz; (void)rc;
    if (tid < 128) {
        float m = snm[tid] ? 1.0f : 0.0f;
        float x = nc[3*tid+0], y = nc[3*tid+1], z = nc[3*tid+2];
        snc[4*tid+0] = x; snc[4*tid+1] = y; snc[4*tid+2] = z; snc[4*tid+3] = m;
        sec[4*tid+0] = ec[3*tid+0]; sec[4*tid+1] = ec[3*tid+1]; sec[4*tid+2] = ec[3*tid+2];
        float xm = x * m, ym = y * m, zm = z * m, cm = m;
        #pragma unroll
        for (int off = 16; off > 0; off >>= 1) {
            xm += __shfl_down_sync(0xFFFFFFFFu, xm, off);
            ym += __shfl_down_sync(0xFFFFFFFFu, ym, off);
            zm += __shfl_down_sync(0xFFFFFFFFu, zm, off);
            cm += __shfl_down_sync(0xFFFFFFFFu, cm, off);
        }
        if (lane == 0) {
            int w = tid >> 5;
            spart[w][0] = xm; spart[w][1] = ym; spart[w][2] = zm; spart[w][3] = cm;
        }
    }
    __syncthreads();
    if (tid == 0) {
        float x = spart[0][0] + spart[1][0] + spart[2][0] + spart[3][0];
        float y = spart[0][1] + spart[1][1] + spart[2][1] + spart[3][1];
        float z = spart[0][2] + spart[1][2] + spart[2][2] + spart[3][2];
        float c = fmaxf(spart[0][3] + spart[1][3] + spart[2][3] + spart[3][3], 1.0f);
        smean[0] = x / c; smean[1] = y / c; smean[2] = z / c;
    }
    __syncthreads();
    if (tid < 128) {
        float m = snc[4*tid+3];
        sfe[4*tid+0] = q[tid] * m;
        sfe[4*tid+1] = (snc[4*tid+0] - smean[0]) * m;
        sfe[4*tid+2] = (snc[4*tid+1] - smean[1]) * m;
        sfe[4*tid+3] = (snc[4*tid+2] - smean[2]) * m;
    }

    // --- dist tile: f32 compute (FMA-pipe sqrt), convert to half2 ONCE ---
    #pragma unroll
    for (int i = tid; i < ME * (MN/2); i += 256) {
        int e = i >> 6, np = i & 63;
        int n0 = np * 2, n1 = n0 + 1;
        float ex0 = sec[4*e+0], ey = sec[4*e+1], ez = sec[4*e+2];
        float dx0 = ex0 - snc[4*n0+0], dy0 = ey - snc[4*n0+1], dz0 = ez - snc[4*n0+2];
        float dx1 = ex0 - snc[4*n1+0], dy1 = ey - snc[4*n1+1], dz1 = ez - snc[4*n1+2];
        float d0 = sqrt_fma(fmaf(dx0, dx0, fmaf(dy0, dy0, dz0*dz0)));
        float d1 = sqrt_fma(fmaf(dx1, dx1, fmaf(dy1, dy1, dz1*dz1)));
        sdh[e * ROWH + np] = __floats2half2_rn(d0, d1);
    }
    __syncthreads();

    // --- single 28-row zl/pi fill as half2 (invalid row zero-padded) ---
    #pragma unroll
    for (int j = tid; j < 28 * (MN/2); j += 256) {
        int ol = j >> 6, np = j & 63;
        int o  = o_start + ol;
        __half2 zl2 = __floats2half2_rn(0.0f, 0.0f);
        __half2 pi2 = zl2;
        if (ol < ow) {
            int n0 = np * 2, n1 = n0 + 1;
            float a0 = sfe[4*n0+0], a1 = sfe[4*n0+1], a2 = sfe[4*n0+2], a3 = sfe[4*n0+3];
            float b0 = sfe[4*n1+0], b1 = sfe[4*n1+1], b2 = sfe[4*n1+2], b3 = sfe[4*n1+3];
            float w0 = Wp[o], w1 = Wp[NO+o], w2 = Wp[2*NO+o], w3 = Wp[3*NO+o];
            float v0 = Wz[o], v1 = Wz[NO+o], v2 = Wz[2*NO+o], v3 = Wz[3*NO+o];
            float zeta0 = fmaf(a0, w0, fmaf(a1, w1, fmaf(a2, w2, a3 * w3)));
            float zeta1 = fmaf(b0, w0, fmaf(b1, w1, fmaf(b2, w2, b3 * w3)));
            float pi0   = fmaf(a0, v0, fmaf(a1, v1, fmaf(a2, v2, a3 * v3)));
            float pi1   = fmaf(b0, v0, fmaf(b1, v1, fmaf(b2, v2, b3 * v3)));
            zl2 = __floats2half2_rn(-fabsf(zeta0) * LOG2E, -fabsf(zeta1) * LOG2E);
            pi2 = __floats2half2_rn(pi0, pi1);
        }
        szlh[ol * ROWH + np] = zl2;
        spih[ol * ROWH + np] = pi2;
    }
    __syncthreads();   // last barrier — maps A and B run back-to-back

    {   // map A: rows 0-15; 4e x 2o per thread; all-fp16 inner loop
        int eg = tid >> 3, og = tid & 7;
        float acc[4][2];
        #pragma unroll
        for (int ei = 0; ei < 4; ei++)
            #pragma unroll
            for (int oj = 0; oj < 2; oj++) acc[ei][oj] = 0.0f;
        const float4* dr0 = (const float4*)(sdh + (eg +  0) * ROWH);
        const float4* dr1 = (const float4*)(sdh + (eg + 32) * ROWH);
        const float4* dr2 = (const float4*)(sdh + (eg + 64) * ROWH);
        const float4* dr3 = (const float4*)(sdh + (eg + 96) * ROWH);
        const float4* zr0 = (const float4*)(szlh + og * ROWH);
        const float4* zr1 = (const float4*)(szlh + (og + 8) * ROWH);
        const float4* pr0 = (const float4*)(spih + og * ROWH);
        const float4* pr1 = (const float4*)(spih + (og + 8) * ROWH);
        #pragma unroll 4
        for (int c = 0; c < 16; c++) {     // 16 float4 = 64 half2 = 128 n
            float4 d0 = dr0[c], d1 = dr1[c], d2 = dr2[c], d3 = dr3[c];
            float4 z0 = zr0[c], p0 = pr0[c];
            acc[0][0] += cell8(d0, z0, p0);
            acc[1][0] += cell8(d1, z0, p0);
            acc[2][0] += cell8(d2, z0, p0);
            acc[3][0] += cell8(d3, z0, p0);
            float4 z1 = zr1[c], p1 = pr1[c];
            acc[0][1] += cell8(d0, z1, p1);
            acc[1][1] += cell8(d1, z1, p1);
            acc[2][1] += cell8(d2, z1, p1);
            acc[3][1] += cell8(d3, z1, p1);
        }
        #pragma unroll
        for (int ei = 0; ei < 4; ei++) {
            int e = eg + 32 * ei;
            bool eok = (sem[e] != 0);
            #pragma unroll
            for (int oj = 0; oj < 2; oj++) {
                int o = o_start + og + 8 * oj;
                int d = o >> 7, m = o & 127;
                float v = (eok && (sem[m] != 0)) ? acc[ei][oj]
                                                 : (e == m ? 1.0f : 0.0f);
                out[(((s << 5) + d) << 14) + (e << 7) + m] = v;
            }
        }
    }
    // no barrier: map B reads rows 16-27, disjoint from map A's rows 0-15

    {   // map B: rows 16-27; 2e x 3o per thread
        int eg2 = tid >> 2, og2 = tid & 3;
        float acc[2][3];
        #pragma unroll
        for (int ei = 0; ei < 2; ei++)
            #pragma unroll
            for (int oj = 0; oj < 3; oj++) acc[ei][oj] = 0.0f;
        const float4* dr0 = (const float4*)(sdh + eg2 * ROWH);
        const float4* dr1 = (const float4*)(sdh + (eg2 + 64) * ROWH);
        #pragma unroll 4
        for (int c = 0; c < 16; c++) {
            float4 d0 = dr0[c], d1 = dr1[c];
            #pragma unroll
            for (int oj = 0; oj < 3; oj++) {
                int row = 16 + og2 + 4 * oj;
                float4 z = ((const float4*)(szlh + row * ROWH))[c];
                float4 p = ((const float4*)(spih + row * ROWH))[c];
                acc[0][oj] += cell8(d0, z, p);
                acc[1][oj] += cell8(d1, z, p);
            }
        }
        int cw = ow - 16;   // 11 or 12
        #pragma unroll
        for (int ei = 0; ei < 2; ei++) {
            int e = eg2 + 64 * ei;
            bool eok = (sem[e] != 0);
            #pragma unroll
            for (int oj = 0; oj < 3; oj++) {
                int ol = og2 + 4 * oj;
                if (ol < cw) {
                    int o = o_start + 16 + ol;
                    int d = o >> 7, m = o & 127;
                    float v = (eok && (sem[m] != 0)) ? acc[ei][oj]
                                                     : (e == m ? 1.0f : 0.0f);
                    out[(((s << 5) + d) << 14) + (e << 7) + m] = v;
                }
            }
        }
    }
}

// ---------------------------------------------------------------------------
extern "C" void kernel_launch(void* const* d_in, const int* in_sizes, int n_in,
                              void* d_out, int out_size) {
    const float* up  = (const float*)d_in[0];
    const float* dn  = (const float*)d_in[1];
    const float* nc  = (const float*)d_in[2];
    const float* q   = (const float*)d_in[3];
    const float* Wpu = (const float*)d_in[4];
    const float* Wzu = (const float*)d_in[5];
    const float* Wpd = (const float*)d_in[6];
    const float* Wzd = (const float*)d_in[7];
    const unsigned char* um = (const unsigned char*)d_in[8];
    const unsigned char* dm = (const unsigned char*)d_in[9];
    const unsigned char* nm = (const unsigned char*)d_in[10];
    float* out = (float*)d_out;

    cudaFuncSetAttribute(k_fused, cudaFuncAttributeMaxDynamicSharedMemorySize,
                         SMEM_FLOATS * sizeof(float));
    k_fused<<<NBLK, 256, SMEM_FLOATS * sizeof(float)>>>(
        up, dn, nc, q, Wpu, Wzu, Wpd, Wzd, um, dm, nm, out);
}

// round 16
// speedup vs baseline: 1.4267x; 1.2051x over previous
#include <cuda_runtime.h>
#include <cuda_bf16.h>
#include <math.h>

#define ME   128
#define MN   128
#define NDET 32
#define NO   (NDET*ME)
#define LOG2E 1.4426950408889634f
#define NBLK 296          // 2 blocks/SM * 148 SMs -> exactly one wave
#define BPS  148

#define ROWP 132          // padded row: stride = 4 banks -> conflict-free LDS.128
#define OFF_SZL (ME*ROWP)
#define OFF_SPI (OFF_SZL + 16*ROWP)
#define OFF_SFE (OFF_SPI + 16*ROWP)
#define OFF_SNC (OFF_SFE + 128*4)
#define OFF_SEC (OFF_SNC + 128*4)
#define SMEM_FLOATS (OFF_SEC + 128*4)   // 90624 B -> 2 blocks/SM

__device__ __forceinline__ float ex2(float x) {
    float y; asm("ex2.approx.ftz.f32 %0, %1;" : "=f"(y) : "f"(x)); return y;
}

// All-FMA/ALU sqrt: Quake rsqrt seed + 2 Newton iters (rel err ~3e-9).
// Keeps dist-tile work off MUFU (the binding pipe).
__device__ __forceinline__ float sqrt_fma(float x) {
    x = fmaxf(x, 1e-20f);
    float y = __int_as_float(0x5f3759df - (__float_as_int(x) >> 1));
    float nh = -0.5f * x;
    y = y * fmaf(nh, y * y, 1.5f);
    y = y * fmaf(nh, y * y, 1.5f);
    return x * y;
}

__device__ __forceinline__ unsigned char mask_val(const unsigned char* p, int i, int mode) {
    if (mode == 2) return (((const float*)p)[i] != 0.0f);
    if (mode == 1) return (((const int*)p)[i] != 0);
    if (mode == 3) return 0;
    return (p[i] != 0);
}

__global__ void __launch_bounds__(256, 2) k_fused(
        const float* __restrict__ up, const float* __restrict__ dn,
        const float* __restrict__ nc, const float* __restrict__ q,
        const float* __restrict__ Wpu, const float* __restrict__ Wzu,
        const float* __restrict__ Wpd, const float* __restrict__ Wzd,
        const unsigned char* __restrict__ um, const unsigned char* __restrict__ dm,
        const unsigned char* __restrict__ nm, float* __restrict__ out) {
    extern __shared__ float smem[];
    float* sd  = smem;
    float* szl = smem + OFF_SZL;
    float* spi = smem + OFF_SPI;
    float* sfe = smem + OFF_SFE;
    float* snc = smem + OFF_SNC;
    float* sec = smem + OFF_SEC;
    __shared__ int   smode[2];
    __shared__ float spart[4][4];        // warp partial sums: x,y,z,cnt
    __shared__ unsigned char sem[128];
    __shared__ unsigned char snm[128];
    __shared__ float smean[3];

    int bx  = blockIdx.x;
    int s   = (bx >= BPS) ? 1 : 0;
    int bl  = bx - s * BPS;
    int tid = threadIdx.x;
    int lane = tid & 31;

    int o_start = (bl * NO) / BPS;       // ragged 27/28-orbital range
    int o_end   = ((bl + 1) * NO) / BPS;

    const float* ec = s ? dn : up;
    const float* Wp = s ? Wpd : Wpu;     // zeta from W_pi
    const float* Wz = s ? Wzd : Wzu;     // pi from W_zeta
    const unsigned char* emp = s ? dm : um;

    // --- mask-mode detection: one warp per mask, ballot-based (no loop) ---
    if (tid < 32 || (tid >= 128 && tid < 160)) {
        const unsigned char* p = (tid < 32) ? emp : nm;
        unsigned int w = ((const unsigned int*)p)[lane];
        unsigned int ex = w & 0x7F800000u;
        bool isf = (w == 0x3F800000u) || (ex >= 0x38000000u && ex <= 0x47000000u);
        unsigned anyF  = __ballot_sync(0xFFFFFFFFu, isf);
        unsigned anyNZ = __ballot_sync(0xFFFFFFFFu, w != 0u);
        unsigned small = __ballot_sync(0xFFFFFFFFu, w <= 1u);
        if (lane == 0) {
            int mode;
            if (!anyNZ)                     mode = 3;
            else if (anyF)                  mode = 2;
            else if (small == 0xFFFFFFFFu)  mode = 1;
            else                            mode = 0;
            smode[tid < 32 ? 0 : 1] = mode;
        }
    }
    __syncthreads();
    if (tid < 128)       sem[tid]       = mask_val(emp, tid, smode[0]);
    else                 snm[tid - 128] = mask_val(nm, tid - 128, smode[1]);
    __syncthreads();

    // --- stage coords; masked mean via warp shuffles (2 barriers total) ---
    if (tid < 128) {
        float m = snm[tid] ? 1.0f : 0.0f;
        float x = nc[3*tid+0], y = nc[3*tid+1], z = nc[3*tid+2];
        snc[4*tid+0] = x; snc[4*tid+1] = y; snc[4*tid+2] = z; snc[4*tid+3] = m;
        sec[4*tid+0] = ec[3*tid+0]; sec[4*tid+1] = ec[3*tid+1]; sec[4*tid+2] = ec[3*tid+2];
        float xm = x * m, ym = y * m, zm = z * m, cm = m;
        #pragma unroll
        for (int off = 16; off > 0; off >>= 1) {
            xm += __shfl_down_sync(0xFFFFFFFFu, xm, off);
            ym += __shfl_down_sync(0xFFFFFFFFu, ym, off);
            zm += __shfl_down_sync(0xFFFFFFFFu, zm, off);
            cm += __shfl_down_sync(0xFFFFFFFFu, cm, off);
        }
        if (lane == 0) {
            int w = tid >> 5;
            spart[w][0] = xm; spart[w][1] = ym; spart[w][2] = zm; spart[w][3] = cm;
        }
    }
    __syncthreads();
    if (tid == 0) {
        float x = spart[0][0] + spart[1][0] + spart[2][0] + spart[3][0];
        float y = spart[0][1] + spart[1][1] + spart[2][1] + spart[3][1];
        float z = spart[0][2] + spart[1][2] + spart[2][2] + spart[3][2];
        float c = fmaxf(spart[0][3] + spart[1][3] + spart[2][3] + spart[3][3], 1.0f);
        smean[0] = x / c; smean[1] = y / c; smean[2] = z / c;
    }
    __syncthreads();
    if (tid < 128) {
        float m = snc[4*tid+3];
        sfe[4*tid+0] = q[tid] * m;
        sfe[4*tid+1] = (snc[4*tid+0] - smean[0]) * m;
        sfe[4*tid+2] = (snc[4*tid+1] - smean[1]) * m;
        sfe[4*tid+3] = (snc[4*tid+2] - smean[2]) * m;
    }

    // --- dist tile [128 e][128 n] (sqrt on FMA/ALU pipes) ---
    #pragma unroll
    for (int i = tid; i < ME * MN; i += 256) {
        int e = i >> 7, n = i & 127;
        float dx = sec[4*e+0] - snc[4*n+0];
        float dy = sec[4*e+1] - snc[4*n+1];
        float dz = sec[4*e+2] - snc[4*n+2];
        sd[e * ROWP + n] = sqrt_fma(fmaf(dx, dx, fmaf(dy, dy, dz*dz)));
    }
    __syncthreads();   // sfe + sd ready

    // ========== chunk 0: 16 orbitals at o_start ==========
    #pragma unroll
    for (int j = tid; j < 16 * MN; j += 256) {
        int ol = j >> 7, n = j & 127;
        int o  = o_start + ol;
        float f0 = sfe[4*n+0], f1 = sfe[4*n+1], f2 = sfe[4*n+2], f3 = sfe[4*n+3];
        float zeta = fmaf(f0, Wp[o], fmaf(f1, Wp[NO+o], fmaf(f2, Wp[2*NO+o], f3 * Wp[3*NO+o])));
        float pi   = fmaf(f0, Wz[o], fmaf(f1, Wz[NO+o], fmaf(f2, Wz[2*NO+o], f3 * Wz[3*NO+o])));
        szl[ol * ROWP + n] = -fabsf(zeta) * LOG2E;
        spi[ol * ROWP + n] = pi;
    }
    __syncthreads();

    {   // map A: 4e x 2o per thread (pure MUFU — proven optimal)
        int eg = tid >> 3, og = tid & 7;
        float acc[4][2];
        #pragma unroll
        for (int ei = 0; ei < 4; ei++)
            #pragma unroll
            for (int oj = 0; oj < 2; oj++) acc[ei][oj] = 0.0f;
        const float* sd0 = sd  + eg * ROWP;
        const float* z0  = szl + og * ROWP;
        const float* p0  = spi + og * ROWP;
        #pragma unroll 4
        for (int c = 0; c < 32; c++) {
            float4 d0 = *(const float4*)(sd0 +  0 * ROWP + c * 4);
            float4 d1 = *(const float4*)(sd0 + 32 * ROWP + c * 4);
            float4 d2 = *(const float4*)(sd0 + 64 * ROWP + c * 4);
            float4 d3 = *(const float4*)(sd0 + 96 * ROWP + c * 4);
            #pragma unroll
            for (int oj = 0; oj < 2; oj++) {
                float4 z = *(const float4*)(z0 + oj * 8 * ROWP + c * 4);
                float4 p = *(const float4*)(p0 + oj * 8 * ROWP + c * 4);
                float4 dd[4] = {d0, d1, d2, d3};
                #pragma unroll
                for (int ei = 0; ei < 4; ei++) {
                    float a = acc[ei][oj];
                    a = fmaf(p.x, ex2(dd[ei].x * z.x), a);
                    a = fmaf(p.y, ex2(dd[ei].y * z.y), a);
                    a = fmaf(p.z, ex2(dd[ei].z * z.z), a);
                    a = fmaf(p.w, ex2(dd[ei].w * z.w), a);
                    acc[ei][oj] = a;
                }
            }
        }
        #pragma unroll
        for (int ei = 0; ei < 4; ei++) {
            int e = eg + 32 * ei;
            bool eok = (sem[e] != 0);
            #pragma unroll
            for (int oj = 0; oj < 2; oj++) {
                int o = o_start + og + 8 * oj;
                int d = o >> 7, m = o & 127;
                float v = (eok && (sem[m] != 0)) ? acc[ei][oj]
                                                 : (e == m ? 1.0f : 0.0f);
                out[(((s << 5) + d) << 14) + (e << 7) + m] = v;
            }
        }
    }
    __syncthreads();

    // ========== chunk 1: up to 12 orbitals at o_start+16 ==========
    int cw = o_end - (o_start + 16);
    #pragma unroll
    for (int j = tid; j < 12 * MN; j += 256) {
        int ol = j >> 7, n = j & 127;
        int o  = o_start + 16 + ol;
        float zl = 0.0f, pi = 0.0f;
        if (ol < cw) {
            float f0 = sfe[4*n+0], f1 = sfe[4*n+1], f2 = sfe[4*n+2], f3 = sfe[4*n+3];
            float zeta = fmaf(f0, Wp[o], fmaf(f1, Wp[NO+o], fmaf(f2, Wp[2*NO+o], f3 * Wp[3*NO+o])));
            pi   = fmaf(f0, Wz[o], fmaf(f1, Wz[NO+o], fmaf(f2, Wz[2*NO+o], f3 * Wz[3*NO+o])));
            zl   = -fabsf(zeta) * LOG2E;
        }
        szl[ol * ROWP + n] = zl;
        spi[ol * ROWP + n] = pi;
    }
    __syncthreads();

    {   // map B: 2e x 3o per thread (pure MUFU)
        int eg2 = tid >> 2, og2 = tid & 3;
        float acc[2][3];
        #pragma unroll
        for (int ei = 0; ei < 2; ei++)
            #pragma unroll
            for (int oj = 0; oj < 3; oj++) acc[ei][oj] = 0.0f;
        const float* sd0 = sd  + eg2 * ROWP;
        const float* z0  = szl + og2 * ROWP;
        const float* p0  = spi + og2 * ROWP;
        #pragma unroll 4
        for (int c = 0; c < 32; c++) {
            float4 d0 = *(const float4*)(sd0 +  0 * ROWP + c * 4);
            float4 d1 = *(const float4*)(sd0 + 64 * ROWP + c * 4);
            #pragma unroll
            for (int oj = 0; oj < 3; oj++) {
                float4 z = *(const float4*)(z0 + oj * 4 * ROWP + c * 4);
                float4 p = *(const float4*)(p0 + oj * 4 * ROWP + c * 4);
                float4 dd[2] = {d0, d1};
                #pragma unroll
                for (int ei = 0; ei < 2; ei++) {
                    float a = acc[ei][oj];
                    a = fmaf(p.x, ex2(dd[ei].x * z.x), a);
                    a = fmaf(p.y, ex2(dd[ei].y * z.y), a);
                    a = fmaf(p.z, ex2(dd[ei].z * z.z), a);
                    a = fmaf(p.w, ex2(dd[ei].w * z.w), a);
                    acc[ei][oj] = a;
                }
            }
        }
        #pragma unroll
        for (int ei = 0; ei < 2; ei++) {
            int e = eg2 + 64 * ei;
            bool eok = (sem[e] != 0);
            #pragma unroll
            for (int oj = 0; oj < 3; oj++) {
                int ol = og2 + 4 * oj;
                if (ol < cw) {
                    int o = o_start + 16 + ol;
                    int d = o >> 7, m = o & 127;
                    float v = (eok && (sem[m] != 0)) ? acc[ei][oj]
                                                     : (e == m ? 1.0f : 0.0f);
                    out[(((s << 5) + d) << 14) + (e << 7) + m] = v;
                }
            }
        }
    }
}

// ---------------------------------------------------------------------------
extern "C" void kernel_launch(void* const* d_in, const int* in_sizes, int n_in,
                              void* d_out, int out_size) {
    const float* up  = (const float*)d_in[0];
    const float* dn  = (const float*)d_in[1];
    const float* nc  = (const float*)d_in[2];
    const float* q   = (const float*)d_in[3];
    const float* Wpu = (const float*)d_in[4];
    const float* Wzu = (const float*)d_in[5];
    const float* Wpd = (const float*)d_in[6];
    const float* Wzd = (const float*)d_in[7];
    const unsigned char* um = (const unsigned char*)d_in[8];
    const unsigned char* dm = (const unsigned char*)d_in[9];
    const unsigned char* nm = (const unsigned char*)d_in[10];
    float* out = (float*)d_out;

    cudaFuncSetAttribute(k_fused, cudaFuncAttributeMaxDynamicSharedMemorySize,
                         SMEM_FLOATS * sizeof(float));
    k_fused<<<NBLK, 256, SMEM_FLOATS * sizeof(float)>>>(
        up, dn, nc, q, Wpu, Wzu, Wpd, Wzd, um, dm, nm, out);
}